// round 15
// baseline (speedup 1.0000x reference)
#include <cuda_runtime.h>
#include <cuda_fp16.h>

#define N_NODES 100000
#define N_EDGES 1600000
#define NEG_SLOPE 0.2f
#define BN_EPS 1e-5f
#define BUCKET 64   // fixed per-node edge capacity; Poisson(16) never exceeds it here

// ---------------- scratch (device globals) ----------------
__device__ float   g_hf[N_NODES * 256];       // projected feats [N,256] fp32 (agg is
                                              // issue-bound, not BW-bound: fp32 kills 8 cvts/edge)
__device__ __half  g_resh[N_NODES * 256];     // residual proj   [N,256] fp16
__device__ __half  g_wh[512 * 128];           // fp16 weights: rows 0-255 fc_w, 256-511 res_w
__device__ float4  g_el[N_NODES];             // [N,4]
__device__ float4  g_er[N_NODES];             // [N,4]
__device__ uint4   g_edge[N_NODES * BUCKET];  // per-dst buckets {src, w01, w23, 0}
__device__ int     g_cursor[N_NODES];
__device__ float4  g_outpre[N_NODES * 16];    // pre-BN output [N,64]
__device__ float   g_bnsum[64];
__device__ float   g_bnsq[64];

// ---------------- kernels ----------------

// zero cursors + convert weights to fp16 (once per call)
__global__ void prep_kernel(const float* __restrict__ fc_w, const float* __restrict__ res_w) {
    int i = blockIdx.x * blockDim.x + threadIdx.x;
    int stride = gridDim.x * blockDim.x;
    for (int idx = i; idx < N_NODES; idx += stride) g_cursor[idx] = 0;
    for (int idx = i; idx < 512 * 128 / 2; idx += stride) {
        int base = idx * 2;
        const float* W = (base < 256 * 128) ? fc_w : res_w;
        int off = (base < 256 * 128) ? base : base - 256 * 128;
        *(__half2*)&g_wh[base] = __floats2half2_rn(W[off], W[off + 1]);
    }
    if (i < 64) { g_bnsum[i] = 0.f; g_bnsq[i] = 0.f; }
}

// Fused tensor-core GEMM, cp.async double-buffered B (fp16 weights from g_wh).
#define A_STRIDE 136
#define B_STRIDE 72
#define B_CHUNK_BYTES (128 * B_STRIDE * 2)   // 18432
#define SMEM_A_OFF 0
#define SMEM_B0_OFF 34816
#define SMEM_EL_OFF (34816 + 2 * B_CHUNK_BYTES)          // 71680
#define SMEM_ER_OFF (SMEM_EL_OFF + 2048)                 // 73728
#define SMEM_GEMM (SMEM_ER_OFF + 2048)                   // 75776
__global__ __launch_bounds__(256) void gemm_tc(const float* __restrict__ feats,
                                               const float* __restrict__ attn_l,
                                               const float* __restrict__ attn_r) {
    extern __shared__ char smem[];
    __half* A_s = (__half*)(smem + SMEM_A_OFF);
    float*  el_s = (float*)(smem + SMEM_EL_OFF);   // [128][4]
    float*  er_s = (float*)(smem + SMEM_ER_OFF);   // [128][4]

    int bm = blockIdx.x;
    int t = threadIdx.x;
    int wid = t >> 5, lane = t & 31;
    int wm = wid & 3, wn = wid >> 2;
    int lq = lane >> 2, lr2 = 2 * (lane & 3);
    int lrow = t >> 1;

    auto issue_b = [&](int chunk) {
        int buf = chunk & 1;
        int cc = chunk >> 1, ks = chunk & 1;
        const __half* wbase = g_wh + (cc * 128) * 128 + ks * 64;
        char* bdst = smem + SMEM_B0_OFF + buf * B_CHUNK_BYTES;
#pragma unroll
        for (int it = 0; it < 4; it++) {
            int id = t + it * 256;
            int r = id >> 3, c8 = id & 7;
            const __half* src = wbase + r * 128 + c8 * 8;
            unsigned saddr = (unsigned)__cvta_generic_to_shared(bdst + r * 144 + c8 * 16);
            asm volatile("cp.async.cg.shared.global [%0], [%1], 16;\n"
                         :: "r"(saddr), "l"(src));
        }
        asm volatile("cp.async.commit_group;\n" ::: "memory");
    };

    issue_b(0);

    {
        long arow = (long)bm * 128 + lrow;
        bool aok = arow < N_NODES;
        const float4* ap = (const float4*)(feats + arow * 128);
#pragma unroll
        for (int i = 0; i < 16; i++) {
            int f4 = (t & 1) * 16 + i;
            float4 v = aok ? ap[f4] : make_float4(0, 0, 0, 0);
            __half2* dp = (__half2*)&A_s[lrow * A_STRIDE + f4 * 4];
            dp[0] = __floats2half2_rn(v.x, v.y);
            dp[1] = __floats2half2_rn(v.z, v.w);
        }
    }

    float acc[2][8][4];
#pragma unroll
    for (int mt = 0; mt < 2; mt++)
#pragma unroll
        for (int nt = 0; nt < 8; nt++)
#pragma unroll
            for (int k = 0; k < 4; k++) acc[mt][nt][k] = 0.f;

    for (int chunk = 0; chunk < 8; chunk++) {
        if (chunk < 7) {
            issue_b(chunk + 1);
            asm volatile("cp.async.wait_group 1;\n" ::: "memory");
        } else {
            asm volatile("cp.async.wait_group 0;\n" ::: "memory");
        }
        __syncthreads();

        const __half* Bbuf = (const __half*)(smem + SMEM_B0_OFF + (chunk & 1) * B_CHUNK_BYTES);
        int ks = chunk & 1;
#pragma unroll
        for (int kc4 = 0; kc4 < 4; kc4++) {
            int kkA = (ks * 4 + kc4) * 16 + lr2;
            int kkB = kc4 * 16 + lr2;
            unsigned b0[8], b1[8];
#pragma unroll
            for (int nt = 0; nt < 8; nt++) {
                int n = wn * 64 + nt * 8 + lq;
                b0[nt] = *(const unsigned*)&Bbuf[n * B_STRIDE + kkB];
                b1[nt] = *(const unsigned*)&Bbuf[n * B_STRIDE + kkB + 8];
            }
#pragma unroll
            for (int mt = 0; mt < 2; mt++) {
                int r = wm * 32 + mt * 16 + lq;
                unsigned a0 = *(const unsigned*)&A_s[r * A_STRIDE + kkA];
                unsigned a1 = *(const unsigned*)&A_s[(r + 8) * A_STRIDE + kkA];
                unsigned a2 = *(const unsigned*)&A_s[r * A_STRIDE + kkA + 8];
                unsigned a3 = *(const unsigned*)&A_s[(r + 8) * A_STRIDE + kkA + 8];
#pragma unroll
                for (int nt = 0; nt < 8; nt++) {
                    asm volatile(
                        "mma.sync.aligned.m16n8k16.row.col.f32.f16.f16.f32 "
                        "{%0,%1,%2,%3}, {%4,%5,%6,%7}, {%8,%9}, {%0,%1,%2,%3};\n"
                        : "+f"(acc[mt][nt][0]), "+f"(acc[mt][nt][1]),
                          "+f"(acc[mt][nt][2]), "+f"(acc[mt][nt][3])
                        : "r"(a0), "r"(a1), "r"(a2), "r"(a3), "r"(b0[nt]), "r"(b1[nt]));
                }
            }
        }

        if (chunk & 1) {
            int cc = chunk >> 1;
            int jbase = (cc & 1) * 128;
            int head = cc * 2 + wn;  // valid for cc<2
#pragma unroll
            for (int mt = 0; mt < 2; mt++) {
                long r0g = (long)bm * 128 + wm * 32 + mt * 16 + lq;
                long r1g = r0g + 8;
                float pl0 = 0.f, pl1 = 0.f, pr0 = 0.f, pr1 = 0.f;
#pragma unroll
                for (int nt = 0; nt < 8; nt++) {
                    int colg = jbase + wn * 64 + nt * 8 + lr2;
                    if (cc < 2) {
                        if (r0g < N_NODES)
                            *(float2*)&g_hf[r0g * 256 + colg] = make_float2(acc[mt][nt][0], acc[mt][nt][1]);
                        if (r1g < N_NODES)
                            *(float2*)&g_hf[r1g * 256 + colg] = make_float2(acc[mt][nt][2], acc[mt][nt][3]);
                        float al0 = attn_l[colg], al1 = attn_l[colg + 1];
                        float ar0 = attn_r[colg], ar1 = attn_r[colg + 1];
                        pl0 += acc[mt][nt][0] * al0 + acc[mt][nt][1] * al1;
                        pl1 += acc[mt][nt][2] * al0 + acc[mt][nt][3] * al1;
                        pr0 += acc[mt][nt][0] * ar0 + acc[mt][nt][1] * ar1;
                        pr1 += acc[mt][nt][2] * ar0 + acc[mt][nt][3] * ar1;
                    } else {
                        if (r0g < N_NODES)
                            *(__half2*)&g_resh[r0g * 256 + colg] = __floats2half2_rn(acc[mt][nt][0], acc[mt][nt][1]);
                        if (r1g < N_NODES)
                            *(__half2*)&g_resh[r1g * 256 + colg] = __floats2half2_rn(acc[mt][nt][2], acc[mt][nt][3]);
                    }
                }
                if (cc < 2) {
#pragma unroll
                    for (int off = 1; off < 4; off <<= 1) {
                        pl0 += __shfl_xor_sync(0xffffffffu, pl0, off);
                        pl1 += __shfl_xor_sync(0xffffffffu, pl1, off);
                        pr0 += __shfl_xor_sync(0xffffffffu, pr0, off);
                        pr1 += __shfl_xor_sync(0xffffffffu, pr1, off);
                    }
                    if ((lane & 3) == 0) {
                        int rloc = wm * 32 + mt * 16 + lq;
                        el_s[rloc * 4 + head] = pl0;
                        el_s[(rloc + 8) * 4 + head] = pl1;
                        er_s[rloc * 4 + head] = pr0;
                        er_s[(rloc + 8) * 4 + head] = pr1;
                    }
                }
            }
#pragma unroll
            for (int mt = 0; mt < 2; mt++)
#pragma unroll
                for (int nt = 0; nt < 8; nt++)
#pragma unroll
                    for (int k = 0; k < 4; k++) acc[mt][nt][k] = 0.f;
        }
        __syncthreads();
    }

    if (t < 128) {
        long row = (long)bm * 128 + t;
        if (row < N_NODES) {
            g_el[row] = *(float4*)&el_s[t * 4];
            g_er[row] = *(float4*)&er_s[t * 4];
        }
    }
}

// bucket scatter: compute exp(leaky(el+er)), pack {src, w01, w23} into one 16B
// record, place in dst's fixed-capacity bucket via per-node atomic cursor.
__global__ void scatter_kernel(const int* __restrict__ src, const int* __restrict__ dst) {
    int i = blockIdx.x * blockDim.x + threadIdx.x;
    int stride = gridDim.x * blockDim.x;
    for (int e = i; e < N_EDGES; e += stride) {
        int s = src[e], d = dst[e];
        float4 l = g_el[s], r = g_er[d];
        float4 x = make_float4(l.x + r.x, l.y + r.y, l.z + r.z, l.w + r.w);
        x.x = x.x > 0.f ? x.x : NEG_SLOPE * x.x;
        x.y = x.y > 0.f ? x.y : NEG_SLOPE * x.y;
        x.z = x.z > 0.f ? x.z : NEG_SLOPE * x.z;
        x.w = x.w > 0.f ? x.w : NEG_SLOPE * x.w;
        __half2 w01 = __floats2half2_rn(__expf(x.x), __expf(x.y));
        __half2 w23 = __floats2half2_rn(__expf(x.z), __expf(x.w));
        uint4 rec;
        rec.x = (unsigned)s;
        rec.y = *(unsigned*)&w01;
        rec.z = *(unsigned*)&w23;
        rec.w = 0u;
        int p = atomicAdd(&g_cursor[d], 1);
        if (p < BUCKET) g_edge[(long)d * BUCKET + p] = rec;
    }
}

// select the needed 16-bit half from a packed half2 word, then ONE cvt
__device__ __forceinline__ float hsel(unsigned w, bool lo) {
    unsigned short u = lo ? (unsigned short)(w & 0xFFFFu) : (unsigned short)(w >> 16);
    return __half2float(__ushort_as_half(u));
}

// packed f32x2 helpers (Blackwell FFMA2 — only reachable via PTX)
__device__ __forceinline__ unsigned long long pack2(float v) {
    unsigned long long r;
    asm("mov.b64 %0, {%1, %1};" : "=l"(r) : "f"(v));
    return r;
}
__device__ __forceinline__ void ffma2(unsigned long long& acc, unsigned long long a,
                                      unsigned long long b) {
    asm("fma.rn.f32x2 %0, %1, %2, %0;" : "+l"(acc) : "l"(a), "l"(b));
}
__device__ __forceinline__ float2 unpack2(unsigned long long v) {
    float2 r;
    asm("mov.b64 {%0, %1}, %2;" : "=f"(r.x), "=f"(r.y) : "l"(v));
    return r;
}

// one warp per dst node: weight-accumulated gather of fp32 h[src] via packed
// FFMA2, normalized at the end; fused residual + bias + ELU + head-mean + BN
// partial sums. Issue-bound kernel: ~16 insts/edge/lane (was ~27 with fp16 h).
__global__ __launch_bounds__(256, 6) void agg_kernel(const float* __restrict__ bias) {
    __shared__ float sh_sum[64], sh_sq[64];
    if (threadIdx.x < 64) { sh_sum[threadIdx.x] = 0.f; sh_sq[threadIdx.x] = 0.f; }
    __syncthreads();
    int warp = (blockIdx.x * blockDim.x + threadIdx.x) >> 5;
    int lane = threadIdx.x & 31;
    int nw = (gridDim.x * blockDim.x) >> 5;
    const float4* bp = (const float4*)bias;
    bool lo16 = lane < 16;

    for (int node = warp; node < N_NODES; node += nw) {
        int deg = g_cursor[node];
        if (deg > BUCKET) deg = BUCKET;
        const uint4* ep = g_edge + (long)node * BUCKET;
        unsigned long long accA01 = 0ull, accA23 = 0ull, accB01 = 0ull, accB23 = 0ull;
        float slo = 0.f, shi = 0.f;
        int j = 0;
        for (; j + 1 < deg; j += 2) {
            uint4 r0 = ep[j], r1 = ep[j + 1];
            const float* h0 = g_hf + (long)(int)r0.x * 256 + 4 * lane;
            const float* h1 = g_hf + (long)(int)r1.x * 256 + 4 * lane;
            ulonglong2 a0 = *(const ulonglong2*)h0;          // ch 4l..4l+3 (heads 0/1)
            ulonglong2 b0 = *(const ulonglong2*)(h0 + 128);  // ch 128+4l.. (heads 2/3)
            ulonglong2 a1 = *(const ulonglong2*)h1;
            ulonglong2 b1 = *(const ulonglong2*)(h1 + 128);
            float alo0 = hsel(r0.y, lo16), ahi0 = hsel(r0.z, lo16);
            float alo1 = hsel(r1.y, lo16), ahi1 = hsel(r1.z, lo16);
            slo += alo0 + alo1; shi += ahi0 + ahi1;
            unsigned long long w;
            w = pack2(alo0); ffma2(accA01, a0.x, w); ffma2(accA23, a0.y, w);
            w = pack2(ahi0); ffma2(accB01, b0.x, w); ffma2(accB23, b0.y, w);
            w = pack2(alo1); ffma2(accA01, a1.x, w); ffma2(accA23, a1.y, w);
            w = pack2(ahi1); ffma2(accB01, b1.x, w); ffma2(accB23, b1.y, w);
        }
        if (j < deg) {
            uint4 r0 = ep[j];
            const float* h0 = g_hf + (long)(int)r0.x * 256 + 4 * lane;
            ulonglong2 a0 = *(const ulonglong2*)h0;
            ulonglong2 b0 = *(const ulonglong2*)(h0 + 128);
            float alo = hsel(r0.y, lo16), ahi = hsel(r0.z, lo16);
            slo += alo; shi += ahi;
            unsigned long long w;
            w = pack2(alo); ffma2(accA01, a0.x, w); ffma2(accA23, a0.y, w);
            w = pack2(ahi); ffma2(accB01, b0.x, w); ffma2(accB23, b0.y, w);
        }
        float2 A01 = unpack2(accA01), A23 = unpack2(accA23);
        float2 B01 = unpack2(accB01), B23 = unpack2(accB23);
        float ilo = (deg > 0) ? 1.f / slo : 0.f;
        float ihi = (deg > 0) ? 1.f / shi : 0.f;
        float4 accA = make_float4(A01.x * ilo, A01.y * ilo, A23.x * ilo, A23.y * ilo);
        float4 accB = make_float4(B01.x * ihi, B01.y * ihi, B23.x * ihi, B23.y * ihi);

        const __half2* rp = (const __half2*)&g_resh[(long)node * 256];
        uint2 q0 = *(const uint2*)(rp + 2 * lane);
        uint2 q1 = *(const uint2*)(rp + 64 + 2 * lane);
        float2 ra = __half22float2(*(__half2*)&q0.x);
        float2 rb = __half22float2(*(__half2*)&q0.y);
        float2 rc = __half22float2(*(__half2*)&q1.x);
        float2 rd = __half22float2(*(__half2*)&q1.y);
        float4 b0 = bp[lane], b1 = bp[32 + lane];
        float4 v0, v1;
        v0.x = accA.x + ra.x + b0.x; v0.y = accA.y + ra.y + b0.y;
        v0.z = accA.z + rb.x + b0.z; v0.w = accA.w + rb.y + b0.w;
        v1.x = accB.x + rc.x + b1.x; v1.y = accB.y + rc.y + b1.y;
        v1.z = accB.z + rd.x + b1.z; v1.w = accB.w + rd.y + b1.w;
        v0.x = v0.x > 0.f ? v0.x : (__expf(v0.x) - 1.f);
        v0.y = v0.y > 0.f ? v0.y : (__expf(v0.y) - 1.f);
        v0.z = v0.z > 0.f ? v0.z : (__expf(v0.z) - 1.f);
        v0.w = v0.w > 0.f ? v0.w : (__expf(v0.w) - 1.f);
        v1.x = v1.x > 0.f ? v1.x : (__expf(v1.x) - 1.f);
        v1.y = v1.y > 0.f ? v1.y : (__expf(v1.y) - 1.f);
        v1.z = v1.z > 0.f ? v1.z : (__expf(v1.z) - 1.f);
        v1.w = v1.w > 0.f ? v1.w : (__expf(v1.w) - 1.f);
        float4 t;
        t.x = v0.x + v1.x; t.y = v0.y + v1.y; t.z = v0.z + v1.z; t.w = v0.w + v1.w;
        float4 u;
        u.x = __shfl_down_sync(0xffffffffu, t.x, 16);
        u.y = __shfl_down_sync(0xffffffffu, t.y, 16);
        u.z = __shfl_down_sync(0xffffffffu, t.z, 16);
        u.w = __shfl_down_sync(0xffffffffu, t.w, 16);
        if (lo16) {
            float4 o;
            o.x = (t.x + u.x) * 0.25f; o.y = (t.y + u.y) * 0.25f;
            o.z = (t.z + u.z) * 0.25f; o.w = (t.w + u.w) * 0.25f;
            g_outpre[(long)node * 16 + lane] = o;
            int d = lane * 4;
            atomicAdd(&sh_sum[d + 0], o.x); atomicAdd(&sh_sum[d + 1], o.y);
            atomicAdd(&sh_sum[d + 2], o.z); atomicAdd(&sh_sum[d + 3], o.w);
            atomicAdd(&sh_sq[d + 0], o.x * o.x); atomicAdd(&sh_sq[d + 1], o.y * o.y);
            atomicAdd(&sh_sq[d + 2], o.z * o.z); atomicAdd(&sh_sq[d + 3], o.w * o.w);
        }
    }
    __syncthreads();
    if (threadIdx.x < 64) {
        atomicAdd(&g_bnsum[threadIdx.x], sh_sum[threadIdx.x]);
        atomicAdd(&g_bnsq[threadIdx.x], sh_sq[threadIdx.x]);
    }
}

// BN finalize (per-block recompute) + normalize + write out
__global__ void norm_kernel(const float* __restrict__ gamma, const float* __restrict__ beta,
                            float* __restrict__ out) {
    __shared__ float sc_s[64], sh_s[64];
    if (threadIdx.x < 64) {
        int d = threadIdx.x;
        float n = (float)N_NODES;
        float mu = g_bnsum[d] / n;
        float var = g_bnsq[d] / n - mu * mu;
        float rs = rsqrtf(var + BN_EPS);
        sc_s[d] = rs * gamma[d];
        sh_s[d] = beta[d] - mu * rs * gamma[d];
    }
    __syncthreads();
    int i = blockIdx.x * blockDim.x + threadIdx.x;
    int stride = gridDim.x * blockDim.x;
    const float4* sp = (const float4*)sc_s;
    const float4* hp = (const float4*)sh_s;
    float4* o4 = (float4*)out;
    for (int idx = i; idx < N_NODES * 16; idx += stride) {
        float4 v = g_outpre[idx];
        int d4 = idx & 15;
        float4 sc = sp[d4], sh = hp[d4];
        v.x = v.x * sc.x + sh.x;
        v.y = v.y * sc.y + sh.y;
        v.z = v.z * sc.z + sh.z;
        v.w = v.w * sc.w + sh.w;
        o4[idx] = v;
    }
}

// ---------------- launch ----------------
extern "C" void kernel_launch(void* const* d_in, const int* in_sizes, int n_in,
                              void* d_out, int out_size) {
    const float* feats  = (const float*)d_in[0];
    const int*   src    = (const int*)d_in[1];   // jnp "int64" is int32 (x64 disabled)
    const int*   dst    = (const int*)d_in[2];
    const float* fc_w   = (const float*)d_in[3];
    const float* attn_l = (const float*)d_in[4];
    const float* attn_r = (const float*)d_in[5];
    const float* res_w  = (const float*)d_in[6];
    const float* bias   = (const float*)d_in[7];
    const float* gamma  = (const float*)d_in[8];
    const float* beta   = (const float*)d_in[9];
    float* out = (float*)d_out;

    cudaFuncSetAttribute(gemm_tc, cudaFuncAttributeMaxDynamicSharedMemorySize, SMEM_GEMM);

    prep_kernel<<<1024, 256>>>(fc_w, res_w);
    gemm_tc<<<782, 256, SMEM_GEMM>>>(feats, attn_l, attn_r);
    scatter_kernel<<<2048, 256>>>(src, dst);
    agg_kernel<<<12500, 256>>>(bias);            // launch index 3 -> ncu profiles THIS
    norm_kernel<<<2048, 256>>>(gamma, beta, out);
}

// round 16
// speedup vs baseline: 1.7307x; 1.7307x over previous
#include <cuda_runtime.h>
#include <cuda_fp16.h>

#define N_NODES 100000
#define N_EDGES 1600000
#define NEG_SLOPE 0.2f
#define BN_EPS 1e-5f
#define BUCKET 64   // fixed per-node edge capacity; Poisson(16) never exceeds it here

// ---------------- scratch (device globals) ----------------
__device__ __half  g_hh[N_NODES * 256];       // projected feats [N,256] fp16 (512B/edge gather
                                              // is the sweet spot: R15 proved fp32 doubles
                                              // wavefronts and regresses 2x)
__device__ __half  g_resh[N_NODES * 256];     // residual proj   [N,256] fp16
__device__ __half  g_wh[512 * 128];           // fp16 weights: rows 0-255 fc_w, 256-511 res_w
__device__ float4  g_el[N_NODES];             // [N,4]
__device__ float4  g_er[N_NODES];             // [N,4]
__device__ uint4   g_edge[N_NODES * BUCKET];  // per-dst buckets {src, w01, w23, 0}
__device__ int     g_cursor[N_NODES];
__device__ float4  g_outpre[N_NODES * 16];    // pre-BN output [N,64]
__device__ float   g_bnsum[64];
__device__ float   g_bnsq[64];

// ---------------- kernels ----------------

// zero cursors + convert weights to fp16 (once per call)
__global__ void prep_kernel(const float* __restrict__ fc_w, const float* __restrict__ res_w) {
    int i = blockIdx.x * blockDim.x + threadIdx.x;
    int stride = gridDim.x * blockDim.x;
    for (int idx = i; idx < N_NODES; idx += stride) g_cursor[idx] = 0;
    for (int idx = i; idx < 512 * 128 / 2; idx += stride) {
        int base = idx * 2;
        const float* W = (base < 256 * 128) ? fc_w : res_w;
        int off = (base < 256 * 128) ? base : base - 256 * 128;
        *(__half2*)&g_wh[base] = __floats2half2_rn(W[off], W[off + 1]);
    }
    if (i < 64) { g_bnsum[i] = 0.f; g_bnsq[i] = 0.f; }
}

// Fused tensor-core GEMM, cp.async double-buffered B (fp16 weights from g_wh).
#define A_STRIDE 136
#define B_STRIDE 72
#define B_CHUNK_BYTES (128 * B_STRIDE * 2)   // 18432
#define SMEM_A_OFF 0
#define SMEM_B0_OFF 34816
#define SMEM_EL_OFF (34816 + 2 * B_CHUNK_BYTES)          // 71680
#define SMEM_ER_OFF (SMEM_EL_OFF + 2048)                 // 73728
#define SMEM_GEMM (SMEM_ER_OFF + 2048)                   // 75776
__global__ __launch_bounds__(256) void gemm_tc(const float* __restrict__ feats,
                                               const float* __restrict__ attn_l,
                                               const float* __restrict__ attn_r) {
    extern __shared__ char smem[];
    __half* A_s = (__half*)(smem + SMEM_A_OFF);
    float*  el_s = (float*)(smem + SMEM_EL_OFF);   // [128][4]
    float*  er_s = (float*)(smem + SMEM_ER_OFF);   // [128][4]

    int bm = blockIdx.x;
    int t = threadIdx.x;
    int wid = t >> 5, lane = t & 31;
    int wm = wid & 3, wn = wid >> 2;
    int lq = lane >> 2, lr2 = 2 * (lane & 3);
    int lrow = t >> 1;

    auto issue_b = [&](int chunk) {
        int buf = chunk & 1;
        int cc = chunk >> 1, ks = chunk & 1;
        const __half* wbase = g_wh + (cc * 128) * 128 + ks * 64;
        char* bdst = smem + SMEM_B0_OFF + buf * B_CHUNK_BYTES;
#pragma unroll
        for (int it = 0; it < 4; it++) {
            int id = t + it * 256;
            int r = id >> 3, c8 = id & 7;
            const __half* src = wbase + r * 128 + c8 * 8;
            unsigned saddr = (unsigned)__cvta_generic_to_shared(bdst + r * 144 + c8 * 16);
            asm volatile("cp.async.cg.shared.global [%0], [%1], 16;\n"
                         :: "r"(saddr), "l"(src));
        }
        asm volatile("cp.async.commit_group;\n" ::: "memory");
    };

    issue_b(0);

    {
        long arow = (long)bm * 128 + lrow;
        bool aok = arow < N_NODES;
        const float4* ap = (const float4*)(feats + arow * 128);
#pragma unroll
        for (int i = 0; i < 16; i++) {
            int f4 = (t & 1) * 16 + i;
            float4 v = aok ? ap[f4] : make_float4(0, 0, 0, 0);
            __half2* dp = (__half2*)&A_s[lrow * A_STRIDE + f4 * 4];
            dp[0] = __floats2half2_rn(v.x, v.y);
            dp[1] = __floats2half2_rn(v.z, v.w);
        }
    }

    float acc[2][8][4];
#pragma unroll
    for (int mt = 0; mt < 2; mt++)
#pragma unroll
        for (int nt = 0; nt < 8; nt++)
#pragma unroll
            for (int k = 0; k < 4; k++) acc[mt][nt][k] = 0.f;

    for (int chunk = 0; chunk < 8; chunk++) {
        if (chunk < 7) {
            issue_b(chunk + 1);
            asm volatile("cp.async.wait_group 1;\n" ::: "memory");
        } else {
            asm volatile("cp.async.wait_group 0;\n" ::: "memory");
        }
        __syncthreads();

        const __half* Bbuf = (const __half*)(smem + SMEM_B0_OFF + (chunk & 1) * B_CHUNK_BYTES);
        int ks = chunk & 1;
#pragma unroll
        for (int kc4 = 0; kc4 < 4; kc4++) {
            int kkA = (ks * 4 + kc4) * 16 + lr2;
            int kkB = kc4 * 16 + lr2;
            unsigned b0[8], b1[8];
#pragma unroll
            for (int nt = 0; nt < 8; nt++) {
                int n = wn * 64 + nt * 8 + lq;
                b0[nt] = *(const unsigned*)&Bbuf[n * B_STRIDE + kkB];
                b1[nt] = *(const unsigned*)&Bbuf[n * B_STRIDE + kkB + 8];
            }
#pragma unroll
            for (int mt = 0; mt < 2; mt++) {
                int r = wm * 32 + mt * 16 + lq;
                unsigned a0 = *(const unsigned*)&A_s[r * A_STRIDE + kkA];
                unsigned a1 = *(const unsigned*)&A_s[(r + 8) * A_STRIDE + kkA];
                unsigned a2 = *(const unsigned*)&A_s[r * A_STRIDE + kkA + 8];
                unsigned a3 = *(const unsigned*)&A_s[(r + 8) * A_STRIDE + kkA + 8];
#pragma unroll
                for (int nt = 0; nt < 8; nt++) {
                    asm volatile(
                        "mma.sync.aligned.m16n8k16.row.col.f32.f16.f16.f32 "
                        "{%0,%1,%2,%3}, {%4,%5,%6,%7}, {%8,%9}, {%0,%1,%2,%3};\n"
                        : "+f"(acc[mt][nt][0]), "+f"(acc[mt][nt][1]),
                          "+f"(acc[mt][nt][2]), "+f"(acc[mt][nt][3])
                        : "r"(a0), "r"(a1), "r"(a2), "r"(a3), "r"(b0[nt]), "r"(b1[nt]));
                }
            }
        }

        if (chunk & 1) {
            int cc = chunk >> 1;
            int jbase = (cc & 1) * 128;
            __half* outp = (cc < 2) ? g_hh : g_resh;
            int head = cc * 2 + wn;  // valid for cc<2
#pragma unroll
            for (int mt = 0; mt < 2; mt++) {
                long r0g = (long)bm * 128 + wm * 32 + mt * 16 + lq;
                long r1g = r0g + 8;
                float pl0 = 0.f, pl1 = 0.f, pr0 = 0.f, pr1 = 0.f;
#pragma unroll
                for (int nt = 0; nt < 8; nt++) {
                    int colg = jbase + wn * 64 + nt * 8 + lr2;
                    if (r0g < N_NODES)
                        *(__half2*)&outp[r0g * 256 + colg] = __floats2half2_rn(acc[mt][nt][0], acc[mt][nt][1]);
                    if (r1g < N_NODES)
                        *(__half2*)&outp[r1g * 256 + colg] = __floats2half2_rn(acc[mt][nt][2], acc[mt][nt][3]);
                    if (cc < 2) {
                        float al0 = attn_l[colg], al1 = attn_l[colg + 1];
                        float ar0 = attn_r[colg], ar1 = attn_r[colg + 1];
                        pl0 += acc[mt][nt][0] * al0 + acc[mt][nt][1] * al1;
                        pl1 += acc[mt][nt][2] * al0 + acc[mt][nt][3] * al1;
                        pr0 += acc[mt][nt][0] * ar0 + acc[mt][nt][1] * ar1;
                        pr1 += acc[mt][nt][2] * ar0 + acc[mt][nt][3] * ar1;
                    }
                }
                if (cc < 2) {
#pragma unroll
                    for (int off = 1; off < 4; off <<= 1) {
                        pl0 += __shfl_xor_sync(0xffffffffu, pl0, off);
                        pl1 += __shfl_xor_sync(0xffffffffu, pl1, off);
                        pr0 += __shfl_xor_sync(0xffffffffu, pr0, off);
                        pr1 += __shfl_xor_sync(0xffffffffu, pr1, off);
                    }
                    if ((lane & 3) == 0) {
                        int rloc = wm * 32 + mt * 16 + lq;
                        el_s[rloc * 4 + head] = pl0;
                        el_s[(rloc + 8) * 4 + head] = pl1;
                        er_s[rloc * 4 + head] = pr0;
                        er_s[(rloc + 8) * 4 + head] = pr1;
                    }
                }
            }
#pragma unroll
            for (int mt = 0; mt < 2; mt++)
#pragma unroll
                for (int nt = 0; nt < 8; nt++)
#pragma unroll
                    for (int k = 0; k < 4; k++) acc[mt][nt][k] = 0.f;
        }
        __syncthreads();
    }

    if (t < 128) {
        long row = (long)bm * 128 + t;
        if (row < N_NODES) {
            g_el[row] = *(float4*)&el_s[t * 4];
            g_er[row] = *(float4*)&er_s[t * 4];
        }
    }
}

// bucket scatter: compute exp(leaky(el+er)), pack {src, w01, w23} into one 16B
// record, place in dst's fixed-capacity bucket via per-node atomic cursor.
__global__ void scatter_kernel(const int* __restrict__ src, const int* __restrict__ dst) {
    int i = blockIdx.x * blockDim.x + threadIdx.x;
    int stride = gridDim.x * blockDim.x;
    for (int e = i; e < N_EDGES; e += stride) {
        int s = src[e], d = dst[e];
        float4 l = g_el[s], r = g_er[d];
        float4 x = make_float4(l.x + r.x, l.y + r.y, l.z + r.z, l.w + r.w);
        x.x = x.x > 0.f ? x.x : NEG_SLOPE * x.x;
        x.y = x.y > 0.f ? x.y : NEG_SLOPE * x.y;
        x.z = x.z > 0.f ? x.z : NEG_SLOPE * x.z;
        x.w = x.w > 0.f ? x.w : NEG_SLOPE * x.w;
        __half2 w01 = __floats2half2_rn(__expf(x.x), __expf(x.y));
        __half2 w23 = __floats2half2_rn(__expf(x.z), __expf(x.w));
        uint4 rec;
        rec.x = (unsigned)s;
        rec.y = *(unsigned*)&w01;
        rec.z = *(unsigned*)&w23;
        rec.w = 0u;
        int p = atomicAdd(&g_cursor[d], 1);
        if (p < BUCKET) g_edge[(long)d * BUCKET + p] = rec;
    }
}

// one warp per dst node, per-lane head ownership: lane l owns channels 8l..8l+7
// (all inside head l>>3), so each edge needs ONE LDG.128 and ONE weight per lane
// (vs 2 loads + 2 weights before). Same 512B/warp/edge traffic, fewer insts.
// Fused residual + bias + ELU + head-mean (shfl butterflies) + BN partials.
__global__ __launch_bounds__(256, 6) void agg_kernel(const float* __restrict__ bias) {
    __shared__ float sh_sum[64], sh_sq[64];
    if (threadIdx.x < 64) { sh_sum[threadIdx.x] = 0.f; sh_sq[threadIdx.x] = 0.f; }
    __syncthreads();
    int warp = (blockIdx.x * blockDim.x + threadIdx.x) >> 5;
    int lane = threadIdx.x & 31;
    int nw = (gridDim.x * blockDim.x) >> 5;
    int wshift = (lane & 8) ? 16 : 0;       // head&1 -> hi half of the packed pair
    bool useZ = (lane & 16) != 0;           // head>=2 -> weights in rec.z

    for (int node = warp; node < N_NODES; node += nw) {
        int deg = g_cursor[node];
        if (deg > BUCKET) deg = BUCKET;
        const uint4* ep = g_edge + (long)node * BUCKET;
        float f0 = 0.f, f1 = 0.f, f2 = 0.f, f3 = 0.f;
        float f4 = 0.f, f5 = 0.f, f6 = 0.f, f7 = 0.f;
        float s = 0.f;
        int j = 0;
        for (; j + 1 < deg; j += 2) {
            uint4 r0 = ep[j], r1 = ep[j + 1];
            const uint4* h0p = (const uint4*)(g_hh + (long)(int)r0.x * 256) + lane;
            const uint4* h1p = (const uint4*)(g_hh + (long)(int)r1.x * 256) + lane;
            uint4 x0 = *h0p;
            uint4 x1 = *h1p;
            unsigned wv0 = useZ ? r0.z : r0.y;
            unsigned wv1 = useZ ? r1.z : r1.y;
            float a0 = __half2float(__ushort_as_half((unsigned short)(wv0 >> wshift)));
            float a1 = __half2float(__ushort_as_half((unsigned short)(wv1 >> wshift)));
            s += a0 + a1;
            float2 p;
            p = __half22float2(*(__half2*)&x0.x); f0 += a0 * p.x; f1 += a0 * p.y;
            p = __half22float2(*(__half2*)&x0.y); f2 += a0 * p.x; f3 += a0 * p.y;
            p = __half22float2(*(__half2*)&x0.z); f4 += a0 * p.x; f5 += a0 * p.y;
            p = __half22float2(*(__half2*)&x0.w); f6 += a0 * p.x; f7 += a0 * p.y;
            p = __half22float2(*(__half2*)&x1.x); f0 += a1 * p.x; f1 += a1 * p.y;
            p = __half22float2(*(__half2*)&x1.y); f2 += a1 * p.x; f3 += a1 * p.y;
            p = __half22float2(*(__half2*)&x1.z); f4 += a1 * p.x; f5 += a1 * p.y;
            p = __half22float2(*(__half2*)&x1.w); f6 += a1 * p.x; f7 += a1 * p.y;
        }
        if (j < deg) {
            uint4 r0 = ep[j];
            const uint4* h0p = (const uint4*)(g_hh + (long)(int)r0.x * 256) + lane;
            uint4 x0 = *h0p;
            unsigned wv0 = useZ ? r0.z : r0.y;
            float a0 = __half2float(__ushort_as_half((unsigned short)(wv0 >> wshift)));
            s += a0;
            float2 p;
            p = __half22float2(*(__half2*)&x0.x); f0 += a0 * p.x; f1 += a0 * p.y;
            p = __half22float2(*(__half2*)&x0.y); f2 += a0 * p.x; f3 += a0 * p.y;
            p = __half22float2(*(__half2*)&x0.z); f4 += a0 * p.x; f5 += a0 * p.y;
            p = __half22float2(*(__half2*)&x0.w); f6 += a0 * p.x; f7 += a0 * p.y;
        }
        float inv = (deg > 0) ? 1.f / s : 0.f;
        f0 *= inv; f1 *= inv; f2 *= inv; f3 *= inv;
        f4 *= inv; f5 *= inv; f6 *= inv; f7 *= inv;

        // residual (fp16, lane's 8 channels) + bias + ELU
        uint4 rx = *((const uint4*)(g_resh + (long)node * 256) + lane);
        float2 ra = __half22float2(*(__half2*)&rx.x);
        float2 rb = __half22float2(*(__half2*)&rx.y);
        float2 rc = __half22float2(*(__half2*)&rx.z);
        float2 rd = __half22float2(*(__half2*)&rx.w);
        const float4* bb = (const float4*)bias + lane * 2;
        float4 b0 = bb[0], b1 = bb[1];
        float v0 = f0 + ra.x + b0.x, v1 = f1 + ra.y + b0.y;
        float v2 = f2 + rb.x + b0.z, v3 = f3 + rb.y + b0.w;
        float v4 = f4 + rc.x + b1.x, v5 = f5 + rc.y + b1.y;
        float v6 = f6 + rd.x + b1.z, v7 = f7 + rd.y + b1.w;
        v0 = v0 > 0.f ? v0 : (__expf(v0) - 1.f);
        v1 = v1 > 0.f ? v1 : (__expf(v1) - 1.f);
        v2 = v2 > 0.f ? v2 : (__expf(v2) - 1.f);
        v3 = v3 > 0.f ? v3 : (__expf(v3) - 1.f);
        v4 = v4 > 0.f ? v4 : (__expf(v4) - 1.f);
        v5 = v5 > 0.f ? v5 : (__expf(v5) - 1.f);
        v6 = v6 > 0.f ? v6 : (__expf(v6) - 1.f);
        v7 = v7 > 0.f ? v7 : (__expf(v7) - 1.f);
        // head mean: sum over the 4 heads (lanes l, l^8, l^16, l^24 share d-offset)
#pragma unroll
        for (int off = 8; off <= 16; off <<= 1) {
            v0 += __shfl_xor_sync(0xffffffffu, v0, off);
            v1 += __shfl_xor_sync(0xffffffffu, v1, off);
            v2 += __shfl_xor_sync(0xffffffffu, v2, off);
            v3 += __shfl_xor_sync(0xffffffffu, v3, off);
            v4 += __shfl_xor_sync(0xffffffffu, v4, off);
            v5 += __shfl_xor_sync(0xffffffffu, v5, off);
            v6 += __shfl_xor_sync(0xffffffffu, v6, off);
            v7 += __shfl_xor_sync(0xffffffffu, v7, off);
        }
        if (lane < 8) {
            float4 o0 = make_float4(v0 * 0.25f, v1 * 0.25f, v2 * 0.25f, v3 * 0.25f);
            float4 o1 = make_float4(v4 * 0.25f, v5 * 0.25f, v6 * 0.25f, v7 * 0.25f);
            g_outpre[(long)node * 16 + lane * 2] = o0;
            g_outpre[(long)node * 16 + lane * 2 + 1] = o1;
            int d = lane * 8;
            atomicAdd(&sh_sum[d + 0], o0.x); atomicAdd(&sh_sum[d + 1], o0.y);
            atomicAdd(&sh_sum[d + 2], o0.z); atomicAdd(&sh_sum[d + 3], o0.w);
            atomicAdd(&sh_sum[d + 4], o1.x); atomicAdd(&sh_sum[d + 5], o1.y);
            atomicAdd(&sh_sum[d + 6], o1.z); atomicAdd(&sh_sum[d + 7], o1.w);
            atomicAdd(&sh_sq[d + 0], o0.x * o0.x); atomicAdd(&sh_sq[d + 1], o0.y * o0.y);
            atomicAdd(&sh_sq[d + 2], o0.z * o0.z); atomicAdd(&sh_sq[d + 3], o0.w * o0.w);
            atomicAdd(&sh_sq[d + 4], o1.x * o1.x); atomicAdd(&sh_sq[d + 5], o1.y * o1.y);
            atomicAdd(&sh_sq[d + 6], o1.z * o1.z); atomicAdd(&sh_sq[d + 7], o1.w * o1.w);
        }
    }
    __syncthreads();
    if (threadIdx.x < 64) {
        atomicAdd(&g_bnsum[threadIdx.x], sh_sum[threadIdx.x]);
        atomicAdd(&g_bnsq[threadIdx.x], sh_sq[threadIdx.x]);
    }
}

// BN finalize (per-block recompute) + normalize + write out
__global__ void norm_kernel(const float* __restrict__ gamma, const float* __restrict__ beta,
                            float* __restrict__ out) {
    __shared__ float sc_s[64], sh_s[64];
    if (threadIdx.x < 64) {
        int d = threadIdx.x;
        float n = (float)N_NODES;
        float mu = g_bnsum[d] / n;
        float var = g_bnsq[d] / n - mu * mu;
        float rs = rsqrtf(var + BN_EPS);
        sc_s[d] = rs * gamma[d];
        sh_s[d] = beta[d] - mu * rs * gamma[d];
    }
    __syncthreads();
    int i = blockIdx.x * blockDim.x + threadIdx.x;
    int stride = gridDim.x * blockDim.x;
    const float4* sp = (const float4*)sc_s;
    const float4* hp = (const float4*)sh_s;
    float4* o4 = (float4*)out;
    for (int idx = i; idx < N_NODES * 16; idx += stride) {
        float4 v = g_outpre[idx];
        int d4 = idx & 15;
        float4 sc = sp[d4], sh = hp[d4];
        v.x = v.x * sc.x + sh.x;
        v.y = v.y * sc.y + sh.y;
        v.z = v.z * sc.z + sh.z;
        v.w = v.w * sc.w + sh.w;
        o4[idx] = v;
    }
}

// ---------------- launch ----------------
extern "C" void kernel_launch(void* const* d_in, const int* in_sizes, int n_in,
                              void* d_out, int out_size) {
    const float* feats  = (const float*)d_in[0];
    const int*   src    = (const int*)d_in[1];   // jnp "int64" is int32 (x64 disabled)
    const int*   dst    = (const int*)d_in[2];
    const float* fc_w   = (const float*)d_in[3];
    const float* attn_l = (const float*)d_in[4];
    const float* attn_r = (const float*)d_in[5];
    const float* res_w  = (const float*)d_in[6];
    const float* bias   = (const float*)d_in[7];
    const float* gamma  = (const float*)d_in[8];
    const float* beta   = (const float*)d_in[9];
    float* out = (float*)d_out;

    cudaFuncSetAttribute(gemm_tc, cudaFuncAttributeMaxDynamicSharedMemorySize, SMEM_GEMM);

    prep_kernel<<<1024, 256>>>(fc_w, res_w);
    gemm_tc<<<782, 256, SMEM_GEMM>>>(feats, attn_l, attn_r);
    scatter_kernel<<<2048, 256>>>(src, dst);
    agg_kernel<<<12500, 256>>>(bias);            // launch index 3 -> ncu profiles THIS
    norm_kernel<<<2048, 256>>>(gamma, beta, out);
}

// round 17
// speedup vs baseline: 1.7499x; 1.0111x over previous
#include <cuda_runtime.h>
#include <cuda_fp16.h>

#define N_NODES 100000
#define N_EDGES 1600000
#define NEG_SLOPE 0.2f
#define BN_EPS 1e-5f
#define BUCKET 64   // fixed per-node edge capacity; Poisson(16) never exceeds it here
#define LOG2E 1.4426950408889634f

// ---------------- scratch (device globals) ----------------
__device__ __half  g_hh[N_NODES * 256];       // projected feats [N,256] fp16
__device__ __half  g_resh[N_NODES * 256];     // residual proj   [N,256] fp16
__device__ __half  g_wh[512 * 128];           // fp16 weights: rows 0-255 fc_w, 256-511 res_w
__device__ float4  g_el[N_NODES];             // [N,4]
__device__ float4  g_er[N_NODES];             // [N,4]
__device__ uint4   g_edge[N_NODES * BUCKET];  // per-dst buckets {src, w01, w23, 0}
__device__ int     g_cursor[N_NODES];
__device__ float4  g_outpre[N_NODES * 16];    // pre-BN output [N,64]
__device__ float   g_bnsum[64];
__device__ float   g_bnsq[64];

// ---------------- kernels ----------------

// convert weights to fp16 + zero BN accumulators (cursor zeroing lives in gemm)
__global__ void prep_kernel(const float* __restrict__ fc_w, const float* __restrict__ res_w) {
    int i = blockIdx.x * blockDim.x + threadIdx.x;
    int stride = gridDim.x * blockDim.x;
    for (int idx = i; idx < 512 * 128 / 2; idx += stride) {
        int base = idx * 2;
        const float* W = (base < 256 * 128) ? fc_w : res_w;
        int off = (base < 256 * 128) ? base : base - 256 * 128;
        *(__half2*)&g_wh[base] = __floats2half2_rn(W[off], W[off + 1]);
    }
    if (i < 64) { g_bnsum[i] = 0.f; g_bnsq[i] = 0.f; }
}

// Fused tensor-core GEMM, cp.async double-buffered B (fp16 weights from g_wh).
#define A_STRIDE 136
#define B_STRIDE 72
#define B_CHUNK_BYTES (128 * B_STRIDE * 2)   // 18432
#define SMEM_A_OFF 0
#define SMEM_B0_OFF 34816
#define SMEM_EL_OFF (34816 + 2 * B_CHUNK_BYTES)          // 71680
#define SMEM_ER_OFF (SMEM_EL_OFF + 2048)                 // 73728
#define SMEM_GEMM (SMEM_ER_OFF + 2048)                   // 75776
__global__ __launch_bounds__(256) void gemm_tc(const float* __restrict__ feats,
                                               const float* __restrict__ attn_l,
                                               const float* __restrict__ attn_r) {
    extern __shared__ char smem[];
    __half* A_s = (__half*)(smem + SMEM_A_OFF);
    float*  el_s = (float*)(smem + SMEM_EL_OFF);   // [128][4]
    float*  er_s = (float*)(smem + SMEM_ER_OFF);   // [128][4]

    int bm = blockIdx.x;
    int t = threadIdx.x;
    int wid = t >> 5, lane = t & 31;
    int wm = wid & 3, wn = wid >> 2;
    int lq = lane >> 2, lr2 = 2 * (lane & 3);
    int lrow = t >> 1;

    // zero this stripe's scatter cursors (replaces a prep pass)
    if (t < 128) {
        long row = (long)bm * 128 + t;
        if (row < N_NODES) g_cursor[row] = 0;
    }

    auto issue_b = [&](int chunk) {
        int buf = chunk & 1;
        int cc = chunk >> 1, ks = chunk & 1;
        const __half* wbase = g_wh + (cc * 128) * 128 + ks * 64;
        char* bdst = smem + SMEM_B0_OFF + buf * B_CHUNK_BYTES;
#pragma unroll
        for (int it = 0; it < 4; it++) {
            int id = t + it * 256;
            int r = id >> 3, c8 = id & 7;
            const __half* src = wbase + r * 128 + c8 * 8;
            unsigned saddr = (unsigned)__cvta_generic_to_shared(bdst + r * 144 + c8 * 16);
            asm volatile("cp.async.cg.shared.global [%0], [%1], 16;\n"
                         :: "r"(saddr), "l"(src));
        }
        asm volatile("cp.async.commit_group;\n" ::: "memory");
    };

    issue_b(0);

    {
        long arow = (long)bm * 128 + lrow;
        bool aok = arow < N_NODES;
        const float4* ap = (const float4*)(feats + arow * 128);
#pragma unroll
        for (int i = 0; i < 16; i++) {
            int f4 = (t & 1) * 16 + i;
            float4 v = aok ? ap[f4] : make_float4(0, 0, 0, 0);
            __half2* dp = (__half2*)&A_s[lrow * A_STRIDE + f4 * 4];
            dp[0] = __floats2half2_rn(v.x, v.y);
            dp[1] = __floats2half2_rn(v.z, v.w);
        }
    }

    float acc[2][8][4];
#pragma unroll
    for (int mt = 0; mt < 2; mt++)
#pragma unroll
        for (int nt = 0; nt < 8; nt++)
#pragma unroll
            for (int k = 0; k < 4; k++) acc[mt][nt][k] = 0.f;

    for (int chunk = 0; chunk < 8; chunk++) {
        if (chunk < 7) {
            issue_b(chunk + 1);
            asm volatile("cp.async.wait_group 1;\n" ::: "memory");
        } else {
            asm volatile("cp.async.wait_group 0;\n" ::: "memory");
        }
        __syncthreads();

        const __half* Bbuf = (const __half*)(smem + SMEM_B0_OFF + (chunk & 1) * B_CHUNK_BYTES);
        int ks = chunk & 1;
#pragma unroll
        for (int kc4 = 0; kc4 < 4; kc4++) {
            int kkA = (ks * 4 + kc4) * 16 + lr2;
            int kkB = kc4 * 16 + lr2;
            unsigned b0[8], b1[8];
#pragma unroll
            for (int nt = 0; nt < 8; nt++) {
                int n = wn * 64 + nt * 8 + lq;
                b0[nt] = *(const unsigned*)&Bbuf[n * B_STRIDE + kkB];
                b1[nt] = *(const unsigned*)&Bbuf[n * B_STRIDE + kkB + 8];
            }
#pragma unroll
            for (int mt = 0; mt < 2; mt++) {
                int r = wm * 32 + mt * 16 + lq;
                unsigned a0 = *(const unsigned*)&A_s[r * A_STRIDE + kkA];
                unsigned a1 = *(const unsigned*)&A_s[(r + 8) * A_STRIDE + kkA];
                unsigned a2 = *(const unsigned*)&A_s[r * A_STRIDE + kkA + 8];
                unsigned a3 = *(const unsigned*)&A_s[(r + 8) * A_STRIDE + kkA + 8];
#pragma unroll
                for (int nt = 0; nt < 8; nt++) {
                    asm volatile(
                        "mma.sync.aligned.m16n8k16.row.col.f32.f16.f16.f32 "
                        "{%0,%1,%2,%3}, {%4,%5,%6,%7}, {%8,%9}, {%0,%1,%2,%3};\n"
                        : "+f"(acc[mt][nt][0]), "+f"(acc[mt][nt][1]),
                          "+f"(acc[mt][nt][2]), "+f"(acc[mt][nt][3])
                        : "r"(a0), "r"(a1), "r"(a2), "r"(a3), "r"(b0[nt]), "r"(b1[nt]));
                }
            }
        }

        if (chunk & 1) {
            int cc = chunk >> 1;
            int jbase = (cc & 1) * 128;
            __half* outp = (cc < 2) ? g_hh : g_resh;
            int head = cc * 2 + wn;  // valid for cc<2
#pragma unroll
            for (int mt = 0; mt < 2; mt++) {
                long r0g = (long)bm * 128 + wm * 32 + mt * 16 + lq;
                long r1g = r0g + 8;
                float pl0 = 0.f, pl1 = 0.f, pr0 = 0.f, pr1 = 0.f;
#pragma unroll
                for (int nt = 0; nt < 8; nt++) {
                    int colg = jbase + wn * 64 + nt * 8 + lr2;
                    if (r0g < N_NODES)
                        *(__half2*)&outp[r0g * 256 + colg] = __floats2half2_rn(acc[mt][nt][0], acc[mt][nt][1]);
                    if (r1g < N_NODES)
                        *(__half2*)&outp[r1g * 256 + colg] = __floats2half2_rn(acc[mt][nt][2], acc[mt][nt][3]);
                    if (cc < 2) {
                        float al0 = attn_l[colg], al1 = attn_l[colg + 1];
                        float ar0 = attn_r[colg], ar1 = attn_r[colg + 1];
                        pl0 += acc[mt][nt][0] * al0 + acc[mt][nt][1] * al1;
                        pl1 += acc[mt][nt][2] * al0 + acc[mt][nt][3] * al1;
                        pr0 += acc[mt][nt][0] * ar0 + acc[mt][nt][1] * ar1;
                        pr1 += acc[mt][nt][2] * ar0 + acc[mt][nt][3] * ar1;
                    }
                }
                if (cc < 2) {
#pragma unroll
                    for (int off = 1; off < 4; off <<= 1) {
                        pl0 += __shfl_xor_sync(0xffffffffu, pl0, off);
                        pl1 += __shfl_xor_sync(0xffffffffu, pl1, off);
                        pr0 += __shfl_xor_sync(0xffffffffu, pr0, off);
                        pr1 += __shfl_xor_sync(0xffffffffu, pr1, off);
                    }
                    if ((lane & 3) == 0) {
                        int rloc = wm * 32 + mt * 16 + lq;
                        el_s[rloc * 4 + head] = pl0;
                        el_s[(rloc + 8) * 4 + head] = pl1;
                        er_s[rloc * 4 + head] = pr0;
                        er_s[(rloc + 8) * 4 + head] = pr1;
                    }
                }
            }
#pragma unroll
            for (int mt = 0; mt < 2; mt++)
#pragma unroll
                for (int nt = 0; nt < 8; nt++)
#pragma unroll
                    for (int k = 0; k < 4; k++) acc[mt][nt][k] = 0.f;
        }
        __syncthreads();
    }

    if (t < 128) {
        long row = (long)bm * 128 + t;
        if (row < N_NODES) {
            g_el[row] = *(float4*)&el_s[t * 4];
            g_er[row] = *(float4*)&er_s[t * 4];
        }
    }
}

// bucket scatter: w = exp(leaky(el+er)) via f16x2 ex2 (2 MUFU-class ops instead
// of 4 fp32 MUFU; leaky(x) = max(x, 0.2x) since slope < 1, scale by log2e
// commutes with max). Pack {src, w01, w23} in one 16B record.
__global__ void scatter_kernel(const int* __restrict__ src, const int* __restrict__ dst) {
    int i = blockIdx.x * blockDim.x + threadIdx.x;
    int stride = gridDim.x * blockDim.x;
    for (int e = i; e < N_EDGES; e += stride) {
        int s = src[e], d = dst[e];
        float4 l = g_el[s], r = g_er[d];
        float m0 = (l.x + r.x) * LOG2E;
        float m1 = (l.y + r.y) * LOG2E;
        float m2 = (l.z + r.z) * LOG2E;
        float m3 = (l.w + r.w) * LOG2E;
        m0 = fmaxf(m0, NEG_SLOPE * m0);
        m1 = fmaxf(m1, NEG_SLOPE * m1);
        m2 = fmaxf(m2, NEG_SLOPE * m2);
        m3 = fmaxf(m3, NEG_SLOPE * m3);
        __half2 h01 = __floats2half2_rn(m0, m1);
        __half2 h23 = __floats2half2_rn(m2, m3);
        unsigned w01, w23;
        asm("ex2.approx.f16x2 %0, %1;" : "=r"(w01) : "r"(*(unsigned*)&h01));
        asm("ex2.approx.f16x2 %0, %1;" : "=r"(w23) : "r"(*(unsigned*)&h23));
        uint4 rec;
        rec.x = (unsigned)s;
        rec.y = w01;
        rec.z = w23;
        rec.w = 0u;
        int p = atomicAdd(&g_cursor[d], 1);
        if (p < BUCKET) g_edge[(long)d * BUCKET + p] = rec;
    }
}

// select the needed 16-bit half from a packed half2 word, then ONE cvt
__device__ __forceinline__ float hsel(unsigned w, bool lo) {
    unsigned short u = lo ? (unsigned short)(w & 0xFFFFu) : (unsigned short)(w >> 16);
    return __half2float(__ushort_as_half(u));
}

__device__ __forceinline__ void acc_edge2(uint2 u0, uint2 u1, float alo, float ahi,
                                          float4& accA, float4& accB) {
    float2 a = __half22float2(*(__half2*)&u0.x);
    float2 b = __half22float2(*(__half2*)&u0.y);
    float2 c = __half22float2(*(__half2*)&u1.x);
    float2 d = __half22float2(*(__half2*)&u1.y);
    accA.x += alo * a.x; accA.y += alo * a.y; accA.z += alo * b.x; accA.w += alo * b.y;
    accB.x += ahi * c.x; accB.y += ahi * c.y; accB.z += ahi * d.x; accB.w += ahi * d.y;
}

// one warp per dst node (R14 layout — empirical optimum; R15/R16 variants both
// regressed): 2-wide unroll, 2xLDG.64 per edge, reg-capped for 6 blocks/SM.
__global__ __launch_bounds__(256, 6) void agg_kernel(const float* __restrict__ bias) {
    __shared__ float sh_sum[64], sh_sq[64];
    if (threadIdx.x < 64) { sh_sum[threadIdx.x] = 0.f; sh_sq[threadIdx.x] = 0.f; }
    __syncthreads();
    int warp = (blockIdx.x * blockDim.x + threadIdx.x) >> 5;
    int lane = threadIdx.x & 31;
    int nw = (gridDim.x * blockDim.x) >> 5;
    const float4* bp = (const float4*)bias;
    bool lo16 = lane < 16;

    for (int node = warp; node < N_NODES; node += nw) {
        int deg = g_cursor[node];
        if (deg > BUCKET) deg = BUCKET;
        const uint4* ep = g_edge + (long)node * BUCKET;
        float4 accA = make_float4(0, 0, 0, 0), accB = make_float4(0, 0, 0, 0);
        float slo = 0.f, shi = 0.f;
        int j = 0;
        for (; j + 1 < deg; j += 2) {
            uint4 r0 = ep[j], r1 = ep[j + 1];
            const __half2* h0p = (const __half2*)&g_hh[(long)(int)r0.x * 256];
            const __half2* h1p = (const __half2*)&g_hh[(long)(int)r1.x * 256];
            uint2 lo0 = *(const uint2*)(h0p + 2 * lane);
            uint2 hi0 = *(const uint2*)(h0p + 64 + 2 * lane);
            uint2 lo1 = *(const uint2*)(h1p + 2 * lane);
            uint2 hi1 = *(const uint2*)(h1p + 64 + 2 * lane);
            float alo0 = hsel(r0.y, lo16), ahi0 = hsel(r0.z, lo16);
            float alo1 = hsel(r1.y, lo16), ahi1 = hsel(r1.z, lo16);
            slo += alo0 + alo1; shi += ahi0 + ahi1;
            acc_edge2(lo0, hi0, alo0, ahi0, accA, accB);
            acc_edge2(lo1, hi1, alo1, ahi1, accA, accB);
        }
        if (j < deg) {
            uint4 r0 = ep[j];
            const __half2* hp = (const __half2*)&g_hh[(long)(int)r0.x * 256];
            uint2 u0 = *(const uint2*)(hp + 2 * lane);
            uint2 u1 = *(const uint2*)(hp + 64 + 2 * lane);
            float alo = hsel(r0.y, lo16), ahi = hsel(r0.z, lo16);
            slo += alo; shi += ahi;
            acc_edge2(u0, u1, alo, ahi, accA, accB);
        }
        float ilo = (deg > 0) ? 1.f / slo : 0.f;
        float ihi = (deg > 0) ? 1.f / shi : 0.f;
        accA.x *= ilo; accA.y *= ilo; accA.z *= ilo; accA.w *= ilo;
        accB.x *= ihi; accB.y *= ihi; accB.z *= ihi; accB.w *= ihi;

        const __half2* rp = (const __half2*)&g_resh[(long)node * 256];
        uint2 q0 = *(const uint2*)(rp + 2 * lane);
        uint2 q1 = *(const uint2*)(rp + 64 + 2 * lane);
        float2 ra = __half22float2(*(__half2*)&q0.x);
        float2 rb = __half22float2(*(__half2*)&q0.y);
        float2 rc = __half22float2(*(__half2*)&q1.x);
        float2 rd = __half22float2(*(__half2*)&q1.y);
        float4 b0 = bp[lane], b1 = bp[32 + lane];
        float4 v0, v1;
        v0.x = accA.x + ra.x + b0.x; v0.y = accA.y + ra.y + b0.y;
        v0.z = accA.z + rb.x + b0.z; v0.w = accA.w + rb.y + b0.w;
        v1.x = accB.x + rc.x + b1.x; v1.y = accB.y + rc.y + b1.y;
        v1.z = accB.z + rd.x + b1.z; v1.w = accB.w + rd.y + b1.w;
        v0.x = v0.x > 0.f ? v0.x : (__expf(v0.x) - 1.f);
        v0.y = v0.y > 0.f ? v0.y : (__expf(v0.y) - 1.f);
        v0.z = v0.z > 0.f ? v0.z : (__expf(v0.z) - 1.f);
        v0.w = v0.w > 0.f ? v0.w : (__expf(v0.w) - 1.f);
        v1.x = v1.x > 0.f ? v1.x : (__expf(v1.x) - 1.f);
        v1.y = v1.y > 0.f ? v1.y : (__expf(v1.y) - 1.f);
        v1.z = v1.z > 0.f ? v1.z : (__expf(v1.z) - 1.f);
        v1.w = v1.w > 0.f ? v1.w : (__expf(v1.w) - 1.f);
        float4 t;
        t.x = v0.x + v1.x; t.y = v0.y + v1.y; t.z = v0.z + v1.z; t.w = v0.w + v1.w;
        float4 u;
        u.x = __shfl_down_sync(0xffffffffu, t.x, 16);
        u.y = __shfl_down_sync(0xffffffffu, t.y, 16);
        u.z = __shfl_down_sync(0xffffffffu, t.z, 16);
        u.w = __shfl_down_sync(0xffffffffu, t.w, 16);
        if (lo16) {
            float4 o;
            o.x = (t.x + u.x) * 0.25f; o.y = (t.y + u.y) * 0.25f;
            o.z = (t.z + u.z) * 0.25f; o.w = (t.w + u.w) * 0.25f;
            g_outpre[(long)node * 16 + lane] = o;
            int d = lane * 4;
            atomicAdd(&sh_sum[d + 0], o.x); atomicAdd(&sh_sum[d + 1], o.y);
            atomicAdd(&sh_sum[d + 2], o.z); atomicAdd(&sh_sum[d + 3], o.w);
            atomicAdd(&sh_sq[d + 0], o.x * o.x); atomicAdd(&sh_sq[d + 1], o.y * o.y);
            atomicAdd(&sh_sq[d + 2], o.z * o.z); atomicAdd(&sh_sq[d + 3], o.w * o.w);
        }
    }
    __syncthreads();
    if (threadIdx.x < 64) {
        atomicAdd(&g_bnsum[threadIdx.x], sh_sum[threadIdx.x]);
        atomicAdd(&g_bnsq[threadIdx.x], sh_sq[threadIdx.x]);
    }
}

// BN finalize (per-block recompute) + normalize + write out
__global__ void norm_kernel(const float* __restrict__ gamma, const float* __restrict__ beta,
                            float* __restrict__ out) {
    __shared__ float sc_s[64], sh_s[64];
    if (threadIdx.x < 64) {
        int d = threadIdx.x;
        float n = (float)N_NODES;
        float mu = g_bnsum[d] / n;
        float var = g_bnsq[d] / n - mu * mu;
        float rs = rsqrtf(var + BN_EPS);
        sc_s[d] = rs * gamma[d];
        sh_s[d] = beta[d] - mu * rs * gamma[d];
    }
    __syncthreads();
    int i = blockIdx.x * blockDim.x + threadIdx.x;
    int stride = gridDim.x * blockDim.x;
    const float4* sp = (const float4*)sc_s;
    const float4* hp = (const float4*)sh_s;
    float4* o4 = (float4*)out;
    for (int idx = i; idx < N_NODES * 16; idx += stride) {
        float4 v = g_outpre[idx];
        int d4 = idx & 15;
        float4 sc = sp[d4], sh = hp[d4];
        v.x = v.x * sc.x + sh.x;
        v.y = v.y * sc.y + sh.y;
        v.z = v.z * sc.z + sh.z;
        v.w = v.w * sc.w + sh.w;
        o4[idx] = v;
    }
}

// ---------------- launch ----------------
extern "C" void kernel_launch(void* const* d_in, const int* in_sizes, int n_in,
                              void* d_out, int out_size) {
    const float* feats  = (const float*)d_in[0];
    const int*   src    = (const int*)d_in[1];   // jnp "int64" is int32 (x64 disabled)
    const int*   dst    = (const int*)d_in[2];
    const float* fc_w   = (const float*)d_in[3];
    const float* attn_l = (const float*)d_in[4];
    const float* attn_r = (const float*)d_in[5];
    const float* res_w  = (const float*)d_in[6];
    const float* bias   = (const float*)d_in[7];
    const float* gamma  = (const float*)d_in[8];
    const float* beta   = (const float*)d_in[9];
    float* out = (float*)d_out;

    cudaFuncSetAttribute(gemm_tc, cudaFuncAttributeMaxDynamicSharedMemorySize, SMEM_GEMM);

    prep_kernel<<<256, 256>>>(fc_w, res_w);
    gemm_tc<<<782, 256, SMEM_GEMM>>>(feats, attn_l, attn_r);
    scatter_kernel<<<2048, 256>>>(src, dst);
    agg_kernel<<<12500, 256>>>(bias);            // launch index 3 -> ncu profiles THIS
    norm_kernel<<<2048, 256>>>(gamma, beta, out);
}